// round 1
// baseline (speedup 1.0000x reference)
#include <cuda_runtime.h>
#include <cuda_bf16.h>
#include <math.h>

// Problem constants
#define BB 64
#define TT 2048
#define DD 512
#define UU 512

// ---------------- device scratch (no allocations allowed) ----------------
__device__ float g_comb[BB * UU];          // W1_b + W2_b + hidden@W2   [B,U]
__device__ float g_scores[BB * TT];        // attention scores          [B,T]
__device__ float g_stats[BB * 2];          // per-b max, sumexp
__device__ float g_partial[BB * 16 * DD];  // split-T context partials

// ---------------- kernel 1: comb[b][u] ----------------
__global__ void comb_kernel(const float* __restrict__ hidden,
                            const float* __restrict__ W2,
                            const float* __restrict__ W1b,
                            const float* __restrict__ W2b) {
    int b = blockIdx.x;
    int u = threadIdx.x;            // 512 threads
    __shared__ float h[DD];
    h[u] = hidden[b * DD + u];
    __syncthreads();
    float acc = W1b[u] + W2b[u];
#pragma unroll 8
    for (int d = 0; d < DD; ++d)
        acc = fmaf(h[d], W2[d * UU + u], acc);
    g_comb[b * UU + u] = acc;
}

// ---------------- kernel 2: fused score GEMM ----------------
// scores[b][t] = sum_u V[u] * tanh( sum_d feat[b,t,d]*W1[d,u] + comb[b,u] )
// Tile: 64 t-rows x 64 u-cols per block, K-tile 16, 256 threads, 4x4 microtile.
#define TM 64
#define TN 64
#define TKK 16

__global__ void __launch_bounds__(256)
score_kernel(const float* __restrict__ feat,
             const float* __restrict__ W1,
             const float* __restrict__ Vw) {
    int b  = blockIdx.y;
    int t0 = blockIdx.x * TM;
    const float* fbase = feat + ((size_t)b * TT + t0) * DD;

    __shared__ float Fs[TKK][TM + 4];   // [k][m], pad 4 keeps 16B alignment
    __shared__ float Ws[TKK][TN + 4];   // [k][n]

    int tid = threadIdx.x;
    int tx = tid & 15;      // col group (4 cols each)
    int ty = tid >> 4;      // row group (4 rows each)

    float sp[4] = {0.f, 0.f, 0.f, 0.f};  // per-row score partials

    for (int n0 = 0; n0 < UU; n0 += TN) {
        // init accumulators with comb (same for all 4 rows of a thread)
        float4 cv = *(const float4*)(&g_comb[b * UU + n0 + (tx << 2)]);
        float acc[4][4];
#pragma unroll
        for (int i = 0; i < 4; ++i) {
            acc[i][0] = cv.x; acc[i][1] = cv.y; acc[i][2] = cv.z; acc[i][3] = cv.w;
        }

        for (int k0 = 0; k0 < DD; k0 += TKK) {
            // load features tile: 64x16 floats, one float4 per thread
            {
                int m  = tid >> 2;
                int kq = (tid & 3) << 2;
                float4 fv = *(const float4*)(fbase + (size_t)m * DD + k0 + kq);
                Fs[kq + 0][m] = fv.x;
                Fs[kq + 1][m] = fv.y;
                Fs[kq + 2][m] = fv.z;
                Fs[kq + 3][m] = fv.w;
            }
            // load W1 tile: 16x64 floats, one float4 per thread
            {
                int kk = tid >> 4;
                int nn = (tid & 15) << 2;
                float4 wv = *(const float4*)(W1 + (size_t)(k0 + kk) * UU + n0 + nn);
                *(float4*)(&Ws[kk][nn]) = wv;
            }
            __syncthreads();

#pragma unroll
            for (int k = 0; k < TKK; ++k) {
                float4 av = *(const float4*)(&Fs[k][ty << 2]);
                float4 wv = *(const float4*)(&Ws[k][tx << 2]);
                float a0 = av.x, a1 = av.y, a2 = av.z, a3 = av.w;
                float w0 = wv.x, w1 = wv.y, w2 = wv.z, w3 = wv.w;
                acc[0][0] = fmaf(a0, w0, acc[0][0]); acc[0][1] = fmaf(a0, w1, acc[0][1]);
                acc[0][2] = fmaf(a0, w2, acc[0][2]); acc[0][3] = fmaf(a0, w3, acc[0][3]);
                acc[1][0] = fmaf(a1, w0, acc[1][0]); acc[1][1] = fmaf(a1, w1, acc[1][1]);
                acc[1][2] = fmaf(a1, w2, acc[1][2]); acc[1][3] = fmaf(a1, w3, acc[1][3]);
                acc[2][0] = fmaf(a2, w0, acc[2][0]); acc[2][1] = fmaf(a2, w1, acc[2][1]);
                acc[2][2] = fmaf(a2, w2, acc[2][2]); acc[2][3] = fmaf(a2, w3, acc[2][3]);
                acc[3][0] = fmaf(a3, w0, acc[3][0]); acc[3][1] = fmaf(a3, w1, acc[3][1]);
                acc[3][2] = fmaf(a3, w2, acc[3][2]); acc[3][3] = fmaf(a3, w3, acc[3][3]);
            }
            __syncthreads();
        }

        // epilogue: tanh + V-weighted reduction over the 4 cols
        float4 vv = *(const float4*)(&Vw[n0 + (tx << 2)]);
        float vr[4] = {vv.x, vv.y, vv.z, vv.w};
#pragma unroll
        for (int i = 0; i < 4; ++i) {
#pragma unroll
            for (int j = 0; j < 4; ++j)
                sp[i] = fmaf(vr[j], tanhf(acc[i][j]), sp[i]);
        }
    }

    // reduce score partials across the 16 col-group threads (16-lane segments)
#pragma unroll
    for (int i = 0; i < 4; ++i) {
        float v = sp[i];
#pragma unroll
        for (int off = 8; off > 0; off >>= 1)
            v += __shfl_down_sync(0xffffffffu, v, off, 16);
        if (tx == 0)
            g_scores[b * TT + t0 + (ty << 2) + i] = v;
    }
}

// ---------------- kernel 3: softmax stats per b ----------------
__global__ void stats_kernel() {
    int b = blockIdx.x;
    int tid = threadIdx.x;  // 256
    __shared__ float red[256];

    float m = -INFINITY;
    for (int t = tid; t < TT; t += 256)
        m = fmaxf(m, g_scores[b * TT + t]);
    red[tid] = m;
    __syncthreads();
    for (int s = 128; s > 0; s >>= 1) {
        if (tid < s) red[tid] = fmaxf(red[tid], red[tid + s]);
        __syncthreads();
    }
    float mx = red[0];
    __syncthreads();

    float sm = 0.f;
    for (int t = tid; t < TT; t += 256)
        sm += expf(g_scores[b * TT + t] - mx);
    red[tid] = sm;
    __syncthreads();
    for (int s = 128; s > 0; s >>= 1) {
        if (tid < s) red[tid] += red[tid + s];
        __syncthreads();
    }
    if (tid == 0) {
        g_stats[b * 2 + 0] = mx;
        g_stats[b * 2 + 1] = red[0];
    }
}

// ---------------- kernel 4: context partials (split T into 16) ----------------
__global__ void ctx_partial_kernel(const float* __restrict__ feat) {
    int b = blockIdx.x;
    int s = blockIdx.y;          // 0..15
    int d = threadIdx.x;         // 512
    __shared__ float w[128];

    float mx  = g_stats[b * 2 + 0];
    float inv = 1.0f / g_stats[b * 2 + 1];
    int t0 = s * 128;

    if (d < 128)
        w[d] = expf(g_scores[b * TT + t0 + d] - mx) * inv;
    __syncthreads();

    float acc = 0.f;
    const float* f = feat + ((size_t)b * TT + t0) * DD + d;
#pragma unroll 4
    for (int t = 0; t < 128; ++t)
        acc = fmaf(w[t], f[(size_t)t * DD], acc);

    g_partial[((size_t)b * 16 + s) * DD + d] = acc;
}

// ---------------- kernel 5: reduce partials -> out ----------------
__global__ void ctx_reduce_kernel(float* __restrict__ out) {
    int b = blockIdx.x;
    int d = threadIdx.x;  // 512
    float acc = 0.f;
#pragma unroll
    for (int s = 0; s < 16; ++s)
        acc += g_partial[((size_t)b * 16 + s) * DD + d];
    out[b * DD + d] = acc;
}

// ---------------- launch ----------------
extern "C" void kernel_launch(void* const* d_in, const int* in_sizes, int n_in,
                              void* d_out, int out_size) {
    const float* features = (const float*)d_in[0];  // [B,T,D]
    const float* hidden   = (const float*)d_in[1];  // [B,D]
    const float* W1_w     = (const float*)d_in[2];  // [D,U]
    const float* W1_b     = (const float*)d_in[3];  // [U]
    const float* W2_w     = (const float*)d_in[4];  // [D,U]
    const float* W2_b     = (const float*)d_in[5];  // [U]
    const float* V_w      = (const float*)d_in[6];  // [U,1]
    // V_b (d_in[7]) is a constant added to every score -> softmax-invariant, ignored.
    float* out = (float*)d_out;                     // [B,D]

    comb_kernel<<<BB, UU>>>(hidden, W2_w, W1_b, W2_b);

    dim3 sgrid(TT / TM, BB);
    score_kernel<<<sgrid, 256>>>(features, W1_w, V_w);

    stats_kernel<<<BB, 256>>>();

    dim3 cgrid(BB, 16);
    ctx_partial_kernel<<<cgrid, DD>>>(features);

    ctx_reduce_kernel<<<BB, DD>>>(out);
}

// round 3
// speedup vs baseline: 2.3776x; 2.3776x over previous
#include <cuda_runtime.h>
#include <cuda_bf16.h>
#include <math.h>
#include <stdint.h>

#define BB 64
#define TT 2048
#define DD 512
#define UU 512

// ---------------- device scratch ----------------
__device__ float g_comb[BB * UU];
__device__ float g_scores[BB * TT];
__device__ float g_spart[2 * BB * TT];
__device__ float g_stats[BB * 2];
__device__ float g_partial[BB * 64 * DD];
__device__ __align__(16) __nv_bfloat16 g_w1t_hi[UU * DD];   // [u][k]
__device__ __align__(16) __nv_bfloat16 g_w1t_lo[UU * DD];
__device__ __align__(16) __nv_bfloat16 g_feat_hi[BB * TT * DD];
__device__ __align__(16) __nv_bfloat16 g_feat_lo[BB * TT * DD];

// ---------------- helpers ----------------
__device__ __forceinline__ uint32_t smem_u32(const void* p) {
    uint32_t a;
    asm("{ .reg .u64 t; cvta.to.shared.u64 t, %1; cvt.u32.u64 %0, t; }" : "=r"(a) : "l"(p));
    return a;
}
__device__ __forceinline__ void cpa16(uint32_t dst, const void* src) {
    asm volatile("cp.async.cg.shared.global [%0], [%1], 16;" :: "r"(dst), "l"(src) : "memory");
}
#define CP_COMMIT() asm volatile("cp.async.commit_group;" ::: "memory")
#define CP_WAIT(n)  asm volatile("cp.async.wait_group %0;" :: "n"(n) : "memory")

#define LDSM4(r, addr) \
    asm volatile("ldmatrix.sync.aligned.m8n8.x4.shared.b16 {%0,%1,%2,%3}, [%4];" \
        : "=r"((r)[0]), "=r"((r)[1]), "=r"((r)[2]), "=r"((r)[3]) : "r"(addr))

__device__ __forceinline__ void mma16816(float* d, const uint32_t* a, const uint32_t* b) {
    asm volatile(
        "mma.sync.aligned.m16n8k16.row.col.f32.bf16.bf16.f32 "
        "{%0,%1,%2,%3}, {%4,%5,%6,%7}, {%8,%9}, {%0,%1,%2,%3};"
        : "+f"(d[0]), "+f"(d[1]), "+f"(d[2]), "+f"(d[3])
        : "r"(a[0]), "r"(a[1]), "r"(a[2]), "r"(a[3]), "r"(b[0]), "r"(b[1]));
}

// ---------------- SMEM layout (score kernel) ----------------
// rows padded to 80B for conflict-free ldmatrix
#define RS 80
#define A_OFF(buf, var) ((uint32_t)((buf) * 20480 + (var) * 10240))
#define B_OFF(buf, var) ((uint32_t)(40960 + (buf) * 40960 + (var) * 20480))
#define OFF_COMB 122880u
#define OFF_V    123904u
#define OFF_SROW 124928u
#define SMEM_SZ  125440u

// ---------------- prep: W1 transpose + split ----------------
__global__ void prep_w1t_kernel(const float* __restrict__ W1) {
    int idx = blockIdx.x * 256 + threadIdx.x;   // 262144
    int k = idx & (DD - 1);
    int u = idx >> 9;
    float x = W1[(size_t)k * UU + u];
    __nv_bfloat16 h = __float2bfloat16(x);
    __nv_bfloat16 l = __float2bfloat16(x - __bfloat162float(h));
    g_w1t_hi[(size_t)u * DD + k] = h;
    g_w1t_lo[(size_t)u * DD + k] = l;
}

// ---------------- prep: features fp32 -> bf16 hi/lo ----------------
__global__ void prep_feat_kernel(const float* __restrict__ feat) {
    size_t i = ((size_t)blockIdx.x * 256 + threadIdx.x) * 4;   // 64M elems / 4
    float4 fv = *(const float4*)(feat + i);
    __nv_bfloat16 h0 = __float2bfloat16(fv.x), h1 = __float2bfloat16(fv.y);
    __nv_bfloat16 h2 = __float2bfloat16(fv.z), h3 = __float2bfloat16(fv.w);
    __nv_bfloat16 l0 = __float2bfloat16(fv.x - __bfloat162float(h0));
    __nv_bfloat16 l1 = __float2bfloat16(fv.y - __bfloat162float(h1));
    __nv_bfloat16 l2 = __float2bfloat16(fv.z - __bfloat162float(h2));
    __nv_bfloat16 l3 = __float2bfloat16(fv.w - __bfloat162float(h3));
    uint2 hv, lv;
    hv.x = (uint32_t)__bfloat16_as_ushort(h0) | ((uint32_t)__bfloat16_as_ushort(h1) << 16);
    hv.y = (uint32_t)__bfloat16_as_ushort(h2) | ((uint32_t)__bfloat16_as_ushort(h3) << 16);
    lv.x = (uint32_t)__bfloat16_as_ushort(l0) | ((uint32_t)__bfloat16_as_ushort(l1) << 16);
    lv.y = (uint32_t)__bfloat16_as_ushort(l2) | ((uint32_t)__bfloat16_as_ushort(l3) << 16);
    *(uint2*)(g_feat_hi + i) = hv;
    *(uint2*)(g_feat_lo + i) = lv;
}

// ---------------- comb[b][u] ----------------
__global__ void comb_kernel(const float* __restrict__ hidden,
                            const float* __restrict__ W2,
                            const float* __restrict__ W1b,
                            const float* __restrict__ W2b) {
    int b = blockIdx.x;
    int u = threadIdx.x;
    __shared__ float h[DD];
    h[u] = hidden[b * DD + u];
    __syncthreads();
    float acc = W1b[u] + W2b[u];
#pragma unroll 8
    for (int d = 0; d < DD; ++d)
        acc = fmaf(h[d], W2[d * UU + u], acc);
    g_comb[b * UU + u] = acc;
}

// ---------------- score GEMM: mma.sync bf16 split x3 ----------------
// grid: (2 nchunk, 16 ttile, 64 b), 512 threads (16 warps, 4M x 4N)
__global__ void __launch_bounds__(512)
score_kernel(const float* __restrict__ Vw) {
    extern __shared__ char smem[];
    uint32_t sb = smem_u32(smem);
    int tid = threadIdx.x;
    int wid = tid >> 5, lane = tid & 31;
    int warpM = wid & 3, warpN = wid >> 2;
    int g = lane >> 2, tg = lane & 3;
    int grp = lane >> 3, r8 = lane & 7;

    int nchunk = blockIdx.x;
    int t0 = blockIdx.y << 7;
    int b = blockIdx.z;
    int u0 = nchunk << 8;

    const __nv_bfloat16* fh = g_feat_hi + ((size_t)b * TT + t0) * DD;
    const __nv_bfloat16* fl = g_feat_lo + ((size_t)b * TT + t0) * DD;
    const __nv_bfloat16* wh = g_w1t_hi + (size_t)u0 * DD;
    const __nv_bfloat16* wl = g_w1t_lo + (size_t)u0 * DD;

    float* comb_s = (float*)(smem + OFF_COMB);
    float* v_s    = (float*)(smem + OFF_V);
    float* srow   = (float*)(smem + OFF_SROW);
    if (tid < 256) {
        comb_s[tid] = g_comb[b * UU + u0 + tid];
        v_s[tid] = Vw[u0 + tid];
    }
    if (tid < 128) srow[tid] = 0.f;

    // per-thread ldmatrix row offsets
    uint32_t rowA = (uint32_t)((r8 + 8 * (grp & 1)) * RS + (grp >> 1) * 16);
    uint32_t rowB = (uint32_t)((r8 + 8 * (grp >> 1)) * RS + (grp & 1) * 16);

    float acc[2][8][4];
#pragma unroll
    for (int i = 0; i < 2; ++i)
#pragma unroll
        for (int j = 0; j < 8; ++j)
#pragma unroll
            for (int q = 0; q < 4; ++q) acc[i][j][q] = 0.f;

    // ---- async load of one k-chunk (32 k) into buffer buf ----
    auto load_chunk = [&](int c, int buf) {
        int k0 = c * 32;
        // A: 2 var x 128 rows x 4 segs = 1024 transfers
#pragma unroll
        for (int i = 0; i < 2; ++i) {
            int idx = tid + 512 * i;
            int var = idx >> 9;
            int rem = idx & 511;
            int row = rem >> 2, seg = rem & 3;
            const __nv_bfloat16* src = (var ? fl : fh) + (size_t)row * DD + k0 + seg * 8;
            cpa16(sb + A_OFF(buf, var) + row * RS + seg * 16, src);
        }
        // B: 2 var x 256 rows x 4 segs = 2048 transfers
#pragma unroll
        for (int i = 0; i < 4; ++i) {
            int idx = tid + 512 * i;
            int var = idx >> 10;
            int rem = idx & 1023;
            int row = rem >> 2, seg = rem & 3;
            const __nv_bfloat16* src = (var ? wl : wh) + (size_t)row * DD + k0 + seg * 8;
            cpa16(sb + B_OFF(buf, var) + row * RS + seg * 16, src);
        }
        CP_COMMIT();
    };

    load_chunk(0, 0);

    for (int c = 0; c < 16; ++c) {
        int buf = c & 1;
        if (c < 15) {
            load_chunk(c + 1, buf ^ 1);
            CP_WAIT(1);
        } else {
            CP_WAIT(0);
        }
        __syncthreads();

        uint32_t aBaseH = sb + A_OFF(buf, 0) + (warpM * 32) * RS + rowA;
        uint32_t aBaseL = sb + A_OFF(buf, 1) + (warpM * 32) * RS + rowA;
        uint32_t bBaseH = sb + B_OFF(buf, 0) + (warpN * 64) * RS + rowB;
        uint32_t bBaseL = sb + B_OFF(buf, 1) + (warpN * 64) * RS + rowB;

#pragma unroll
        for (int k16 = 0; k16 < 2; ++k16) {
            uint32_t ahi[2][4], alo[2][4];
#pragma unroll
            for (int mt = 0; mt < 2; ++mt) {
                LDSM4(ahi[mt], aBaseH + mt * (16 * RS) + k16 * 32);
                LDSM4(alo[mt], aBaseL + mt * (16 * RS) + k16 * 32);
            }
#pragma unroll
            for (int nt = 0; nt < 4; ++nt) {
                uint32_t bh[4], bl[4];
                LDSM4(bh, bBaseH + nt * (16 * RS) + k16 * 32);
                LDSM4(bl, bBaseL + nt * (16 * RS) + k16 * 32);
#pragma unroll
                for (int mt = 0; mt < 2; ++mt) {
                    mma16816(acc[mt][nt * 2],     ahi[mt], bh);
                    mma16816(acc[mt][nt * 2],     ahi[mt], bl);
                    mma16816(acc[mt][nt * 2],     alo[mt], bh);
                    mma16816(acc[mt][nt * 2 + 1], ahi[mt], bh + 2);
                    mma16816(acc[mt][nt * 2 + 1], ahi[mt], bl + 2);
                    mma16816(acc[mt][nt * 2 + 1], alo[mt], bh + 2);
                }
            }
        }
        __syncthreads();
    }

    // ---- epilogue: V * tanh(acc + comb), reduce to per-row score ----
#pragma unroll
    for (int mt = 0; mt < 2; ++mt) {
        float s0 = 0.f, s1 = 0.f;
#pragma unroll
        for (int nt = 0; nt < 8; ++nt) {
#pragma unroll
            for (int j = 0; j < 2; ++j) {
                int ul = warpN * 64 + nt * 8 + tg * 2 + j;
                float cb = comb_s[ul], vv = v_s[ul];
                s0 = fmaf(vv, tanhf(acc[mt][nt][j] + cb), s0);
                s1 = fmaf(vv, tanhf(acc[mt][nt][2 + j] + cb), s1);
            }
        }
        s0 += __shfl_xor_sync(0xffffffffu, s0, 1);
        s0 += __shfl_xor_sync(0xffffffffu, s0, 2);
        s1 += __shfl_xor_sync(0xffffffffu, s1, 1);
        s1 += __shfl_xor_sync(0xffffffffu, s1, 2);
        if (tg == 0) {
            int row = warpM * 32 + mt * 16 + g;
            atomicAdd(&srow[row], s0);
            atomicAdd(&srow[row + 8], s1);
        }
    }
    __syncthreads();
    if (tid < 128)
        g_spart[(size_t)nchunk * BB * TT + b * TT + t0 + tid] = srow[tid];
}

// ---------------- softmax stats + score combine ----------------
__global__ void stats_kernel() {
    int b = blockIdx.x;
    int tid = threadIdx.x;   // 256
    __shared__ float red[256];
    float m = -INFINITY;
    for (int t = tid; t < TT; t += 256) {
        float s = g_spart[b * TT + t] + g_spart[BB * TT + b * TT + t];
        g_scores[b * TT + t] = s;
        m = fmaxf(m, s);
    }
    red[tid] = m;
    __syncthreads();
    for (int s = 128; s > 0; s >>= 1) {
        if (tid < s) red[tid] = fmaxf(red[tid], red[tid + s]);
        __syncthreads();
    }
    float mx = red[0];
    __syncthreads();
    float sm = 0.f;
    for (int t = tid; t < TT; t += 256)
        sm += expf(g_scores[b * TT + t] - mx);
    red[tid] = sm;
    __syncthreads();
    for (int s = 128; s > 0; s >>= 1) {
        if (tid < s) red[tid] += red[tid + s];
        __syncthreads();
    }
    if (tid == 0) { g_stats[b * 2] = mx; g_stats[b * 2 + 1] = red[0]; }
}

// ---------------- context partials ----------------
__global__ void __launch_bounds__(512)
ctx_partial_kernel(const float* __restrict__ feat) {
    int b = blockIdx.x;
    int s = blockIdx.y;
    int tid = threadIdx.x;
    __shared__ float w[128];
    float mx = g_stats[b * 2], inv = 1.0f / g_stats[b * 2 + 1];
    int t0 = s * 128;
    if (tid < 128)
        w[tid] = expf(g_scores[b * TT + t0 + tid] - mx) * inv;
    __syncthreads();
    int tl = tid >> 7;
    int dq = (tid & 127) << 2;
    float4 acc = make_float4(0.f, 0.f, 0.f, 0.f);
    const float* fb = feat + ((size_t)b * TT + t0) * DD;
#pragma unroll 4
    for (int i = 0; i < 32; ++i) {
        int t = tl + (i << 2);
        float4 f = *(const float4*)(fb + (size_t)t * DD + dq);
        float ww = w[t];
        acc.x = fmaf(ww, f.x, acc.x);
        acc.y = fmaf(ww, f.y, acc.y);
        acc.z = fmaf(ww, f.z, acc.z);
        acc.w = fmaf(ww, f.w, acc.w);
    }
    *(float4*)(&g_partial[((((size_t)b * 16 + s) * 4) + tl) * DD + dq]) = acc;
}

__global__ void ctx_reduce_kernel(float* __restrict__ out) {
    int b = blockIdx.x;
    int d = threadIdx.x;
    float a = 0.f;
#pragma unroll
    for (int s = 0; s < 64; ++s)
        a += g_partial[((size_t)b * 64 + s) * DD + d];
    out[b * DD + d] = a;
}

// ---------------- launch ----------------
extern "C" void kernel_launch(void* const* d_in, const int* in_sizes, int n_in,
                              void* d_out, int out_size) {
    const float* features = (const float*)d_in[0];
    const float* hidden   = (const float*)d_in[1];
    const float* W1_w     = (const float*)d_in[2];
    const float* W1_b     = (const float*)d_in[3];
    const float* W2_w     = (const float*)d_in[4];
    const float* W2_b     = (const float*)d_in[5];
    const float* V_w      = (const float*)d_in[6];
    // V_b: constant shift, softmax-invariant -> dropped
    float* out = (float*)d_out;

    cudaFuncSetAttribute(score_kernel, cudaFuncAttributeMaxDynamicSharedMemorySize, SMEM_SZ);

    prep_w1t_kernel<<<1024, 256>>>(W1_w);
    prep_feat_kernel<<<BB * TT * DD / 1024, 256>>>(features);
    comb_kernel<<<BB, UU>>>(hidden, W2_w, W1_b, W2_b);

    dim3 sgrid(2, 16, BB);
    score_kernel<<<sgrid, 512, SMEM_SZ>>>(V_w);

    stats_kernel<<<BB, 256>>>();
    dim3 cgrid(BB, 16);
    ctx_partial_kernel<<<cgrid, 512>>>(features);
    ctx_reduce_kernel<<<BB, DD>>>(out);
}

// round 4
// speedup vs baseline: 2.8682x; 1.2064x over previous
#include <cuda_runtime.h>
#include <cuda_fp16.h>
#include <math.h>
#include <stdint.h>

#define BB 64
#define TT 2048
#define DD 512
#define UU 512

// ---------------- device scratch ----------------
__device__ float g_comb[BB * UU];
__device__ float g_scores[BB * TT];
__device__ float g_spart[2 * BB * TT];
__device__ float g_stats[BB * 2];
__device__ float g_partial[BB * 64 * DD];
// A fragments: [b][t16 0..127][k16 0..31][lane 0..31] -> uint4 (a0,a1,a2,a3) fp16x2
__device__ uint4 g_afrag[BB * 128 * 32 * 32];
// B fragments: [n8 0..63][k16 0..31][lane 0..31] -> uint4 (bh0,bh1,bl0,bl1)
__device__ uint4 g_bfrag[64 * 32 * 32];

// ---------------- helpers ----------------
__device__ __forceinline__ uint32_t pack_h2(float x, float y) {
    __half2 h = __floats2half2_rn(x, y);
    return *(uint32_t*)&h;
}

__device__ __forceinline__ void mma_f16(float* d, const uint4& a, uint32_t b0, uint32_t b1) {
    asm volatile(
        "mma.sync.aligned.m16n8k16.row.col.f32.f16.f16.f32 "
        "{%0,%1,%2,%3}, {%4,%5,%6,%7}, {%8,%9}, {%0,%1,%2,%3};"
        : "+f"(d[0]), "+f"(d[1]), "+f"(d[2]), "+f"(d[3])
        : "r"(a.x), "r"(a.y), "r"(a.z), "r"(a.w), "r"(b0), "r"(b1));
}

// ---------------- prep: features fp32 -> fp16 fragment-major ----------------
// one thread per (b,t16,k16,lane): writes uint4
__global__ void prep_afrag_kernel(const float* __restrict__ feat) {
    int gidx = blockIdx.x * 256 + threadIdx.x;      // 8388608
    int lane = gidx & 31;
    int k16 = (gidx >> 5) & 31;
    int t16 = (gidx >> 10) & 127;
    int b = gidx >> 17;
    int g = lane >> 2, tg = lane & 3;
    int tA = t16 * 16 + g;
    int kA = k16 * 16 + 2 * tg;
    const float* base = feat + ((size_t)b * TT) * DD;
    float2 f00 = *(const float2*)(base + (size_t)tA * DD + kA);
    float2 f10 = *(const float2*)(base + (size_t)(tA + 8) * DD + kA);
    float2 f01 = *(const float2*)(base + (size_t)tA * DD + kA + 8);
    float2 f11 = *(const float2*)(base + (size_t)(tA + 8) * DD + kA + 8);
    uint4 o;
    o.x = pack_h2(f00.x, f00.y);   // a0: row g,   k 2tg..
    o.y = pack_h2(f10.x, f10.y);   // a1: row g+8, k 2tg..
    o.z = pack_h2(f01.x, f01.y);   // a2: row g,   k 2tg+8..
    o.w = pack_h2(f11.x, f11.y);   // a3: row g+8, k 2tg+8..
    g_afrag[gidx] = o;
}

// ---------------- prep: W1 -> split fp16 fragment-major ----------------
// one thread per (n8,k16,lane)
__global__ void prep_bfrag_kernel(const float* __restrict__ W1) {
    int gidx = blockIdx.x * 256 + threadIdx.x;      // 65536
    int lane = gidx & 31;
    int k16 = (gidx >> 5) & 31;
    int n8 = gidx >> 10;
    int g = lane >> 2, tg = lane & 3;
    int u = n8 * 8 + g;
    int k = k16 * 16 + 2 * tg;
    float x0 = W1[(size_t)k * UU + u];
    float x1 = W1[(size_t)(k + 1) * UU + u];
    float x2 = W1[(size_t)(k + 8) * UU + u];
    float x3 = W1[(size_t)(k + 9) * UU + u];
    __half h0 = __float2half_rn(x0), h1 = __float2half_rn(x1);
    __half h2 = __float2half_rn(x2), h3 = __float2half_rn(x3);
    float l0 = x0 - __half2float(h0), l1 = x1 - __half2float(h1);
    float l2 = x2 - __half2float(h2), l3 = x3 - __half2float(h3);
    uint4 o;
    o.x = (uint32_t)*(uint16_t*)&h0 | ((uint32_t)*(uint16_t*)&h1 << 16);  // bh0
    o.y = (uint32_t)*(uint16_t*)&h2 | ((uint32_t)*(uint16_t*)&h3 << 16);  // bh1
    o.z = pack_h2(l0, l1);                                                 // bl0
    o.w = pack_h2(l2, l3);                                                 // bl1
    g_bfrag[gidx] = o;
}

// ---------------- comb[b][u] ----------------
__global__ void comb_kernel(const float* __restrict__ hidden,
                            const float* __restrict__ W2,
                            const float* __restrict__ W1b,
                            const float* __restrict__ W2b) {
    int b = blockIdx.x;
    int u = threadIdx.x;
    __shared__ float h[DD];
    h[u] = hidden[b * DD + u];
    __syncthreads();
    float acc = W1b[u] + W2b[u];
#pragma unroll 8
    for (int d = 0; d < DD; ++d)
        acc = fmaf(h[d], W2[d * UU + u], acc);
    g_comb[b * UU + u] = acc;
}

// ---------------- score GEMM: gmem-direct fragments, no smem pipeline ----------------
// grid (2 nchunk, 16 ttile, 64 b), 512 threads = 16 warps (4 warpM x 4 warpN)
// warp tile: 32 t-rows (mt 0,1 of 16) x 64 u-cols (nt 0..7 of 8)
__global__ void __launch_bounds__(512)
score_kernel(const float* __restrict__ Vw) {
    __shared__ float comb_s[256];
    __shared__ float v_s[256];
    __shared__ float srow[128];

    int tid = threadIdx.x;
    int wid = tid >> 5, lane = tid & 31;
    int warpM = wid & 3, warpN = wid >> 2;
    int g = lane >> 2, tg = lane & 3;

    int nchunk = blockIdx.x;
    int t0 = blockIdx.y << 7;
    int b = blockIdx.z;
    int u0 = nchunk << 8;

    if (tid < 256) {
        comb_s[tid] = g_comb[b * UU + u0 + tid];
        v_s[tid] = Vw[u0 + tid];
    }
    if (tid < 128) srow[tid] = 0.f;

    // A fragment pointers: index ((b*128+tt)*32+k16)*32+lane
    int tt0 = (t0 >> 4) + warpM * 2;     // mt adds +1
    const uint4* pA0 = g_afrag + (((size_t)(b * 128 + tt0) * 32) * 32 + lane);
    const uint4* pA1 = pA0 + 32 * 32;    // mt=1
    // B fragment pointers: index ((n8*32+k16)*32+lane), n8 = nchunk*32 + warpN*8 + nt
    const uint4* pB = g_bfrag + (((size_t)(nchunk * 32 + warpN * 8) * 32) * 32 + lane);

    float acc[2][8][4];
#pragma unroll
    for (int i = 0; i < 2; ++i)
#pragma unroll
        for (int j = 0; j < 8; ++j)
#pragma unroll
            for (int q = 0; q < 4; ++q) acc[i][j][q] = 0.f;

#pragma unroll 2
    for (int k16 = 0; k16 < 32; ++k16) {
        uint4 A0 = pA0[k16 * 32];
        uint4 A1 = pA1[k16 * 32];
        uint4 Bc = pB[k16 * 32];
#pragma unroll
        for (int nt = 0; nt < 8; ++nt) {
            uint4 Bn;
            if (nt < 7) Bn = pB[(nt + 1) * 1024 + k16 * 32];
            mma_f16(acc[0][nt], A0, Bc.x, Bc.y);   // hi
            mma_f16(acc[0][nt], A0, Bc.z, Bc.w);   // lo
            mma_f16(acc[1][nt], A1, Bc.x, Bc.y);
            mma_f16(acc[1][nt], A1, Bc.z, Bc.w);
            Bc = Bn;
        }
    }

    __syncthreads();   // srow/comb_s/v_s ready; mainloop done

    // ---- epilogue: s = sum_u v[u] * tanh(acc + comb[u]) ----
    float s[4] = {0.f, 0.f, 0.f, 0.f};   // (mt0,g),(mt0,g+8),(mt1,g),(mt1,g+8)
#pragma unroll
    for (int nt = 0; nt < 8; ++nt) {
#pragma unroll
        for (int j = 0; j < 2; ++j) {
            int ul = warpN * 64 + nt * 8 + 2 * tg + j;
            float cb = comb_s[ul], vv = v_s[ul];
            s[0] = fmaf(vv, tanhf(acc[0][nt][j] + cb), s[0]);
            s[1] = fmaf(vv, tanhf(acc[0][nt][2 + j] + cb), s[1]);
            s[2] = fmaf(vv, tanhf(acc[1][nt][j] + cb), s[2]);
            s[3] = fmaf(vv, tanhf(acc[1][nt][2 + j] + cb), s[3]);
        }
    }
#pragma unroll
    for (int i = 0; i < 4; ++i) {
        s[i] += __shfl_xor_sync(0xffffffffu, s[i], 1);
        s[i] += __shfl_xor_sync(0xffffffffu, s[i], 2);
    }
    if (tg == 0) {
        int rbase = warpM * 32;
        atomicAdd(&srow[rbase + g], s[0]);
        atomicAdd(&srow[rbase + g + 8], s[1]);
        atomicAdd(&srow[rbase + 16 + g], s[2]);
        atomicAdd(&srow[rbase + 16 + g + 8], s[3]);
    }
    __syncthreads();
    if (tid < 128)
        g_spart[(size_t)nchunk * BB * TT + b * TT + t0 + tid] = srow[tid];
}

// ---------------- softmax stats + score combine ----------------
__global__ void stats_kernel() {
    int b = blockIdx.x;
    int tid = threadIdx.x;   // 256
    __shared__ float red[256];
    float m = -INFINITY;
    for (int t = tid; t < TT; t += 256) {
        float sc = g_spart[b * TT + t] + g_spart[BB * TT + b * TT + t];
        g_scores[b * TT + t] = sc;
        m = fmaxf(m, sc);
    }
    red[tid] = m;
    __syncthreads();
    for (int s = 128; s > 0; s >>= 1) {
        if (tid < s) red[tid] = fmaxf(red[tid], red[tid + s]);
        __syncthreads();
    }
    float mx = red[0];
    __syncthreads();
    float sm = 0.f;
    for (int t = tid; t < TT; t += 256)
        sm += expf(g_scores[b * TT + t] - mx);
    red[tid] = sm;
    __syncthreads();
    for (int s = 128; s > 0; s >>= 1) {
        if (tid < s) red[tid] += red[tid + s];
        __syncthreads();
    }
    if (tid == 0) { g_stats[b * 2] = mx; g_stats[b * 2 + 1] = red[0]; }
}

// ---------------- context partials ----------------
__global__ void __launch_bounds__(512)
ctx_partial_kernel(const float* __restrict__ feat) {
    int b = blockIdx.x;
    int s = blockIdx.y;
    int tid = threadIdx.x;
    __shared__ float w[128];
    float mx = g_stats[b * 2], inv = 1.0f / g_stats[b * 2 + 1];
    int t0 = s * 128;
    if (tid < 128)
        w[tid] = expf(g_scores[b * TT + t0 + tid] - mx) * inv;
    __syncthreads();
    int tl = tid >> 7;
    int dq = (tid & 127) << 2;
    float4 acc = make_float4(0.f, 0.f, 0.f, 0.f);
    const float* fb = feat + ((size_t)b * TT + t0) * DD;
#pragma unroll 4
    for (int i = 0; i < 32; ++i) {
        int t = tl + (i << 2);
        float4 f = *(const float4*)(fb + (size_t)t * DD + dq);
        float ww = w[t];
        acc.x = fmaf(ww, f.x, acc.x);
        acc.y = fmaf(ww, f.y, acc.y);
        acc.z = fmaf(ww, f.z, acc.z);
        acc.w = fmaf(ww, f.w, acc.w);
    }
    *(float4*)(&g_partial[((((size_t)b * 16 + s) * 4) + tl) * DD + dq]) = acc;
}

__global__ void ctx_reduce_kernel(float* __restrict__ out) {
    int b = blockIdx.x;
    int d = threadIdx.x;
    float a = 0.f;
#pragma unroll
    for (int s = 0; s < 64; ++s)
        a += g_partial[((size_t)b * 64 + s) * DD + d];
    out[b * DD + d] = a;
}

// ---------------- launch ----------------
extern "C" void kernel_launch(void* const* d_in, const int* in_sizes, int n_in,
                              void* d_out, int out_size) {
    const float* features = (const float*)d_in[0];
    const float* hidden   = (const float*)d_in[1];
    const float* W1_w     = (const float*)d_in[2];
    const float* W1_b     = (const float*)d_in[3];
    const float* W2_w     = (const float*)d_in[4];
    const float* W2_b     = (const float*)d_in[5];
    const float* V_w      = (const float*)d_in[6];
    // V_b: constant shift, softmax-invariant -> dropped
    float* out = (float*)d_out;

    prep_afrag_kernel<<<BB * 128 * 32 * 32 / 256, 256>>>(features);
    prep_bfrag_kernel<<<64 * 32 * 32 / 256, 256>>>(W1_w);
    comb_kernel<<<BB, UU>>>(hidden, W2_w, W1_b, W2_b);

    dim3 sgrid(2, 16, BB);
    score_kernel<<<sgrid, 512>>>(V_w);

    stats_kernel<<<BB, 256>>>();
    dim3 cgrid(BB, 16);
    ctx_partial_kernel<<<cgrid, 512>>>(features);
    ctx_reduce_kernel<<<BB, DD>>>(out);
}

// round 5
// speedup vs baseline: 5.0282x; 1.7531x over previous
#include <cuda_runtime.h>
#include <cuda_fp16.h>
#include <math.h>
#include <stdint.h>

#define BB 64
#define TT 2048
#define DD 512
#define UU 512

// ---------------- device scratch ----------------
__device__ float g_comb[BB * UU];
__device__ float g_scores[BB * TT];
__device__ float g_spart[2 * BB * TT];
__device__ float g_stats[BB * 2];
__device__ float g_partial[BB * 64 * DD];
// A fragments: [b][t16 0..127][k16 0..31][lane 0..31] -> uint4 (a0,a1,a2,a3) fp16x2
__device__ uint4 g_afrag[BB * 128 * 32 * 32];
// B fragments (single fp16, 2 n8 per uint4): [n4 0..31][k16 0..31][lane 0..31]
//   uint4 = (b0,b1 of n8=2*n4, b0,b1 of n8=2*n4+1)
__device__ uint4 g_bfrag[32 * 32 * 32];

// ---------------- helpers ----------------
__device__ __forceinline__ uint32_t pack_h2(float x, float y) {
    __half2 h = __floats2half2_rn(x, y);
    return *(uint32_t*)&h;
}

__device__ __forceinline__ void mma_f16(float* d, const uint4& a, uint32_t b0, uint32_t b1) {
    asm volatile(
        "mma.sync.aligned.m16n8k16.row.col.f32.f16.f16.f32 "
        "{%0,%1,%2,%3}, {%4,%5,%6,%7}, {%8,%9}, {%0,%1,%2,%3};"
        : "+f"(d[0]), "+f"(d[1]), "+f"(d[2]), "+f"(d[3])
        : "r"(a.x), "r"(a.y), "r"(a.z), "r"(a.w), "r"(b0), "r"(b1));
}

// ---------------- prep: features fp32 -> fp16 fragment-major ----------------
__global__ void prep_afrag_kernel(const float* __restrict__ feat) {
    int gidx = blockIdx.x * 256 + threadIdx.x;      // 8388608
    int lane = gidx & 31;
    int k16 = (gidx >> 5) & 31;
    int t16 = (gidx >> 10) & 127;
    int b = gidx >> 17;
    int g = lane >> 2, tg = lane & 3;
    int tA = t16 * 16 + g;
    int kA = k16 * 16 + 2 * tg;
    const float* base = feat + ((size_t)b * TT) * DD;
    float2 f00 = *(const float2*)(base + (size_t)tA * DD + kA);
    float2 f10 = *(const float2*)(base + (size_t)(tA + 8) * DD + kA);
    float2 f01 = *(const float2*)(base + (size_t)tA * DD + kA + 8);
    float2 f11 = *(const float2*)(base + (size_t)(tA + 8) * DD + kA + 8);
    uint4 o;
    o.x = pack_h2(f00.x, f00.y);
    o.y = pack_h2(f10.x, f10.y);
    o.z = pack_h2(f01.x, f01.y);
    o.w = pack_h2(f11.x, f11.y);
    g_afrag[gidx] = o;
}

// ---------------- prep: W1 -> fp16 fragment-major (2 n8 per uint4) ----------------
__global__ void prep_bfrag_kernel(const float* __restrict__ W1) {
    int gidx = blockIdx.x * 256 + threadIdx.x;      // 32768
    int lane = gidx & 31;
    int k16 = (gidx >> 5) & 31;
    int n4 = gidx >> 10;
    int g = lane >> 2, tg = lane & 3;
    int k = k16 * 16 + 2 * tg;
    int ua = (2 * n4) * 8 + g;
    int ub = (2 * n4 + 1) * 8 + g;
    uint4 o;
    o.x = pack_h2(W1[(size_t)k * UU + ua],       W1[(size_t)(k + 1) * UU + ua]);
    o.y = pack_h2(W1[(size_t)(k + 8) * UU + ua], W1[(size_t)(k + 9) * UU + ua]);
    o.z = pack_h2(W1[(size_t)k * UU + ub],       W1[(size_t)(k + 1) * UU + ub]);
    o.w = pack_h2(W1[(size_t)(k + 8) * UU + ub], W1[(size_t)(k + 9) * UU + ub]);
    g_bfrag[gidx] = o;
}

// ---------------- comb[b][u] ----------------
__global__ void comb_kernel(const float* __restrict__ hidden,
                            const float* __restrict__ W2,
                            const float* __restrict__ W1b,
                            const float* __restrict__ W2b) {
    int b = blockIdx.x;
    int u = threadIdx.x;
    __shared__ float h[DD];
    h[u] = hidden[b * DD + u];
    __syncthreads();
    float acc = W1b[u] + W2b[u];
#pragma unroll 8
    for (int d = 0; d < DD; ++d)
        acc = fmaf(h[d], W2[d * UU + u], acc);
    g_comb[b * UU + u] = acc;
}

// ---------------- score GEMM: single fp16 product, reg double-buffer ----------------
// grid (2 nchunk, 16 ttile, 64 b), 512 threads = 16 warps (4 warpM x 4 warpN)
// warp tile: 32 t-rows x 64 u-cols; per k16: 16 HMMA, 6 LDG.128 (prefetched 1 k16 ahead)
__global__ void __launch_bounds__(512)
score_kernel(const float* __restrict__ Vw) {
    __shared__ float comb_s[256];
    __shared__ float v_s[256];
    __shared__ float srow[128];

    int tid = threadIdx.x;
    int wid = tid >> 5, lane = tid & 31;
    int warpM = wid & 3, warpN = wid >> 2;
    int g = lane >> 2, tg = lane & 3;

    int nchunk = blockIdx.x;
    int t0 = blockIdx.y << 7;
    int b = blockIdx.z;
    int u0 = nchunk << 8;

    if (tid < 256) {
        comb_s[tid] = g_comb[b * UU + u0 + tid];
        v_s[tid] = Vw[u0 + tid];
    }
    if (tid < 128) srow[tid] = 0.f;

    int tt0 = (t0 >> 4) + warpM * 2;
    const uint4* pA0 = g_afrag + (((size_t)(b * 128 + tt0) * 32) * 32 + lane);
    const uint4* pA1 = pA0 + 32 * 32;
    const uint4* pB  = g_bfrag + (((size_t)(nchunk * 16 + warpN * 4) * 32) * 32 + lane);

    float acc[2][8][4];
#pragma unroll
    for (int i = 0; i < 2; ++i)
#pragma unroll
        for (int j = 0; j < 8; ++j)
#pragma unroll
            for (int q = 0; q < 4; ++q) acc[i][j][q] = 0.f;

    uint4 Ab[2][2], Bb[2][4];
    Ab[0][0] = pA0[0];
    Ab[0][1] = pA1[0];
#pragma unroll
    for (int j = 0; j < 4; ++j) Bb[0][j] = pB[j * 1024];

#pragma unroll 2
    for (int k16 = 0; k16 < 32; ++k16) {
        int cur = k16 & 1, nxt = cur ^ 1;
        if (k16 < 31) {
            int off = (k16 + 1) * 32;
            Ab[nxt][0] = pA0[off];
            Ab[nxt][1] = pA1[off];
#pragma unroll
            for (int j = 0; j < 4; ++j) Bb[nxt][j] = pB[j * 1024 + off];
        }
#pragma unroll
        for (int n4 = 0; n4 < 4; ++n4) {
            uint4 B4 = Bb[cur][n4];
            mma_f16(acc[0][2 * n4],     Ab[cur][0], B4.x, B4.y);
            mma_f16(acc[0][2 * n4 + 1], Ab[cur][0], B4.z, B4.w);
            mma_f16(acc[1][2 * n4],     Ab[cur][1], B4.x, B4.y);
            mma_f16(acc[1][2 * n4 + 1], Ab[cur][1], B4.z, B4.w);
        }
    }

    __syncthreads();

    // ---- epilogue: s = sum_u v[u] * tanh(acc + comb[u]) ----
    float s[4] = {0.f, 0.f, 0.f, 0.f};
#pragma unroll
    for (int nt = 0; nt < 8; ++nt) {
#pragma unroll
        for (int j = 0; j < 2; ++j) {
            int ul = warpN * 64 + nt * 8 + 2 * tg + j;
            float cb = comb_s[ul], vv = v_s[ul];
            s[0] = fmaf(vv, tanhf(acc[0][nt][j] + cb), s[0]);
            s[1] = fmaf(vv, tanhf(acc[0][nt][2 + j] + cb), s[1]);
            s[2] = fmaf(vv, tanhf(acc[1][nt][j] + cb), s[2]);
            s[3] = fmaf(vv, tanhf(acc[1][nt][2 + j] + cb), s[3]);
        }
    }
#pragma unroll
    for (int i = 0; i < 4; ++i) {
        s[i] += __shfl_xor_sync(0xffffffffu, s[i], 1);
        s[i] += __shfl_xor_sync(0xffffffffu, s[i], 2);
    }
    if (tg == 0) {
        int rbase = warpM * 32;
        atomicAdd(&srow[rbase + g], s[0]);
        atomicAdd(&srow[rbase + g + 8], s[1]);
        atomicAdd(&srow[rbase + 16 + g], s[2]);
        atomicAdd(&srow[rbase + 16 + g + 8], s[3]);
    }
    __syncthreads();
    if (tid < 128)
        g_spart[(size_t)nchunk * BB * TT + b * TT + t0 + tid] = srow[tid];
}

// ---------------- softmax stats + score combine ----------------
__global__ void stats_kernel() {
    int b = blockIdx.x;
    int tid = threadIdx.x;   // 256
    __shared__ float red[256];
    float m = -INFINITY;
    for (int t = tid; t < TT; t += 256) {
        float sc = g_spart[b * TT + t] + g_spart[BB * TT + b * TT + t];
        g_scores[b * TT + t] = sc;
        m = fmaxf(m, sc);
    }
    red[tid] = m;
    __syncthreads();
    for (int s = 128; s > 0; s >>= 1) {
        if (tid < s) red[tid] = fmaxf(red[tid], red[tid + s]);
        __syncthreads();
    }
    float mx = red[0];
    __syncthreads();
    float sm = 0.f;
    for (int t = tid; t < TT; t += 256)
        sm += expf(g_scores[b * TT + t] - mx);
    red[tid] = sm;
    __syncthreads();
    for (int s = 128; s > 0; s >>= 1) {
        if (tid < s) red[tid] += red[tid + s];
        __syncthreads();
    }
    if (tid == 0) { g_stats[b * 2] = mx; g_stats[b * 2 + 1] = red[0]; }
}

// ---------------- context partials ----------------
__global__ void __launch_bounds__(512)
ctx_partial_kernel(const float* __restrict__ feat) {
    int b = blockIdx.x;
    int s = blockIdx.y;
    int tid = threadIdx.x;
    __shared__ float w[128];
    float mx = g_stats[b * 2], inv = 1.0f / g_stats[b * 2 + 1];
    int t0 = s * 128;
    if (tid < 128)
        w[tid] = expf(g_scores[b * TT + t0 + tid] - mx) * inv;
    __syncthreads();
    int tl = tid >> 7;
    int dq = (tid & 127) << 2;
    float4 acc = make_float4(0.f, 0.f, 0.f, 0.f);
    const float* fb = feat + ((size_t)b * TT + t0) * DD;
#pragma unroll 4
    for (int i = 0; i < 32; ++i) {
        int t = tl + (i << 2);
        float4 f = *(const float4*)(fb + (size_t)t * DD + dq);
        float ww = w[t];
        acc.x = fmaf(ww, f.x, acc.x);
        acc.y = fmaf(ww, f.y, acc.y);
        acc.z = fmaf(ww, f.z, acc.z);
        acc.w = fmaf(ww, f.w, acc.w);
    }
    *(float4*)(&g_partial[((((size_t)b * 16 + s) * 4) + tl) * DD + dq]) = acc;
}

__global__ void ctx_reduce_kernel(float* __restrict__ out) {
    int b = blockIdx.x;
    int d = threadIdx.x;
    float a = 0.f;
#pragma unroll
    for (int s = 0; s < 64; ++s)
        a += g_partial[((size_t)b * 64 + s) * DD + d];
    out[b * DD + d] = a;
}

// ---------------- launch ----------------
extern "C" void kernel_launch(void* const* d_in, const int* in_sizes, int n_in,
                              void* d_out, int out_size) {
    const float* features = (const float*)d_in[0];
    const float* hidden   = (const float*)d_in[1];
    const float* W1_w     = (const float*)d_in[2];
    const float* W1_b     = (const float*)d_in[3];
    const float* W2_w     = (const float*)d_in[4];
    const float* W2_b     = (const float*)d_in[5];
    const float* V_w      = (const float*)d_in[6];
    // V_b: constant shift, softmax-invariant -> dropped
    float* out = (float*)d_out;

    prep_afrag_kernel<<<BB * 128 * 32 * 32 / 256, 256>>>(features);
    prep_bfrag_kernel<<<32 * 32 * 32 / 256, 256>>>(W1_w);
    comb_kernel<<<BB, UU>>>(hidden, W2_w, W1_b, W2_b);

    dim3 sgrid(2, 16, BB);
    score_kernel<<<sgrid, 512>>>(V_w);

    stats_kernel<<<BB, 256>>>();
    dim3 cgrid(BB, 16);
    ctx_partial_kernel<<<cgrid, 512>>>(features);
    ctx_reduce_kernel<<<BB, DD>>>(out);
}